// round 15
// baseline (speedup 1.0000x reference)
#include <cuda_runtime.h>
#include <cuda_bf16.h>
#include <cstdint>

#define B_   4
#define C_   128
#define CQ_  16
#define N_   4096

__device__ __nv_bfloat16 g_q[B_ * N_ * CQ_];   // [B][N][16]  (q pre-scaled by log2e)
__device__ __nv_bfloat16 g_k[B_ * N_ * CQ_];   // [B][N][16]
__device__ __nv_bfloat16 g_v[B_ * C_ * N_];    // [B][C][N]  (channel-major)

extern __shared__ char dyn_smem[];

// ---------------------------------------------------------------------------
// Helpers
// ---------------------------------------------------------------------------
__device__ __forceinline__ uint32_t smem_to_u32(const void* p) {
    uint32_t a;
    asm("{ .reg .u64 t; cvta.to.shared.u64 t, %1; cvt.u32.u64 %0, t; }"
        : "=r"(a) : "l"(p));
    return a;
}
__device__ __forceinline__ void cp_async16(uint32_t dst, const void* src) {
    asm volatile("cp.async.cg.shared.global [%0], [%1], 16;"
                 :: "r"(dst), "l"(src) : "memory");
}
__device__ __forceinline__ void cp_commit() {
    asm volatile("cp.async.commit_group;" ::: "memory");
}
__device__ __forceinline__ void cp_wait0() {
    asm volatile("cp.async.wait_group 0;" ::: "memory");
}
__device__ __forceinline__ uint32_t lds32(uint32_t addr) {
    uint32_t v;
    asm volatile("ld.shared.b32 %0, [%1];" : "=r"(v) : "r"(addr));
    return v;
}
__device__ __forceinline__ void ldsm_x4(uint32_t* r, uint32_t addr) {
    asm volatile("ldmatrix.sync.aligned.m8n8.x4.shared.b16 {%0,%1,%2,%3}, [%4];"
                 : "=r"(r[0]), "=r"(r[1]), "=r"(r[2]), "=r"(r[3]) : "r"(addr));
}
__device__ __forceinline__ void ldsm_x4_trans(uint32_t* r, uint32_t addr) {
    asm volatile("ldmatrix.sync.aligned.m8n8.x4.trans.shared.b16 {%0,%1,%2,%3}, [%4];"
                 : "=r"(r[0]), "=r"(r[1]), "=r"(r[2]), "=r"(r[3]) : "r"(addr));
}
__device__ __forceinline__ void mma16816(float* d, const uint32_t* a,
                                         uint32_t b0, uint32_t b1) {
    asm volatile(
        "mma.sync.aligned.m16n8k16.row.col.f32.bf16.bf16.f32 "
        "{%0,%1,%2,%3}, {%4,%5,%6,%7}, {%8,%9}, {%0,%1,%2,%3};"
        : "+f"(d[0]), "+f"(d[1]), "+f"(d[2]), "+f"(d[3])
        : "r"(a[0]), "r"(a[1]), "r"(a[2]), "r"(a[3]), "r"(b0), "r"(b1));
}
__device__ __forceinline__ uint32_t ex2_bf16x2(uint32_t x) {
    uint32_t d;
    asm("ex2.approx.ftz.bf16x2 %0, %1;" : "=r"(d) : "r"(x));
    return d;
}
__device__ __forceinline__ void bar_sync(int id, int cnt) {
    asm volatile("bar.sync %0, %1;" :: "r"(id), "r"(cnt) : "memory");
}
// pack: low half = a, high half = b
#define CVT_BF16X2_F32(result, a, b) \
    asm("cvt.rn.satfinite.bf16x2.f32 %0, %1, %2;" : "=r"(result) : "f"(b), "f"(a))

#define ONES_BF16X2 0x3F803F80u

// ---------------------------------------------------------------------------
// Projection on tensor cores (q pre-scaled by log2e) — unchanged
// ---------------------------------------------------------------------------
#define PJ_WS   0
#define PJ_XS   43520
#define PJ_BS   78336
#define PROJ_SM_BYTES (PJ_BS + 640)
#define LOG2E_F 1.44269504088896f

__global__ __launch_bounds__(256, 1)
void proj_kernel(const float* __restrict__ x,
                 const float* __restrict__ wq, const float* __restrict__ bq,
                 const float* __restrict__ wk, const float* __restrict__ bk,
                 const float* __restrict__ wv, const float* __restrict__ bv) {
    char* sm = dyn_smem;
    const uint32_t smb = smem_to_u32(sm);
    __nv_bfloat16* Ws = (__nv_bfloat16*)(sm + PJ_WS);
    __nv_bfloat16* Xs = (__nv_bfloat16*)(sm + PJ_XS);
    float* Bs = (float*)(sm + PJ_BS);

    const int tid = threadIdx.x;
    const int b   = blockIdx.y;
    const int n0  = blockIdx.x * 128;

    for (int idx = tid; idx < 160 * 32; idx += 256) {
        int ch = idx >> 5, cq = (idx & 31) * 4;
        const float* wsrc = (ch < 16) ? (wq + ch * 128 + cq)
                          : (ch < 32) ? (wk + (ch - 16) * 128 + cq)
                                      : (wv + (ch - 32) * 128 + cq);
        float4 wv4 = *(const float4*)wsrc;
        if (ch < 16) {
            wv4.x *= LOG2E_F; wv4.y *= LOG2E_F;
            wv4.z *= LOG2E_F; wv4.w *= LOG2E_F;
        }
        uint32_t p0, p1;
        CVT_BF16X2_F32(p0, wv4.x, wv4.y);
        CVT_BF16X2_F32(p1, wv4.z, wv4.w);
        *(uint2*)(Ws + ch * 136 + cq) = make_uint2(p0, p1);
    }
    if (tid < 160)
        Bs[tid] = (tid < 16) ? (bq[tid] * LOG2E_F)
                : (tid < 32) ? bk[tid - 16] : bv[tid - 32];

    const float* xb = x + (size_t)b * C_ * N_ + n0;
    for (int idx = tid; idx < 128 * 32; idx += 256) {
        int c = idx >> 5, jq = (idx & 31) * 4;
        float4 xv = *(const float4*)(xb + (size_t)c * N_ + jq);
        uint32_t p0, p1;
        CVT_BF16X2_F32(p0, xv.x, xv.y);
        CVT_BF16X2_F32(p1, xv.z, xv.w);
        *(uint2*)(Xs + c * 136 + jq) = make_uint2(p0, p1);
    }
    __syncthreads();

    const int w  = tid >> 5;
    const int l  = tid & 31;
    const int gr = l >> 2, qd = l & 3;
    const int grp = l >> 3, lr = l & 7;
    const int nw = 16 * w;

    float acc[10][2][4];
    #pragma unroll
    for (int mf = 0; mf < 10; mf++)
        #pragma unroll
        for (int nf = 0; nf < 2; nf++)
            #pragma unroll
            for (int i = 0; i < 4; i++) acc[mf][nf][i] = 0.f;

    const uint32_t xbase = smb + PJ_XS
        + (uint32_t)((grp & 1) * 8 + lr) * 272u + (uint32_t)(nw + (grp >> 1) * 8) * 2u;
    const uint32_t wbase = smb + PJ_WS
        + (uint32_t)((grp & 1) * 8 + lr) * 272u + (uint32_t)((grp >> 1) * 8) * 2u;

    #pragma unroll
    for (int kk = 0; kk < 8; kk++) {
        uint32_t bx[4];
        ldsm_x4_trans(bx, xbase + kk * 16 * 272u);
        #pragma unroll
        for (int mf = 0; mf < 10; mf++) {
            uint32_t aw[4];
            ldsm_x4(aw, wbase + (uint32_t)(mf * 16) * 272u + kk * 32u);
            mma16816(acc[mf][0], aw, bx[0], bx[1]);
            mma16816(acc[mf][1], aw, bx[2], bx[3]);
        }
    }

    #pragma unroll
    for (int mf = 0; mf < 10; mf++) {
        int ch0 = 16 * mf + gr;
        float b0 = Bs[ch0], b1 = Bs[ch0 + 8];
        #pragma unroll
        for (int nf = 0; nf < 2; nf++) {
            int pos = n0 + nw + 8 * nf + 2 * qd;
            float v00 = acc[mf][nf][0] + b0, v01 = acc[mf][nf][1] + b0;
            float v10 = acc[mf][nf][2] + b1, v11 = acc[mf][nf][3] + b1;
            if (mf == 0) {
                g_q[(size_t)(b * N_ + pos) * 16 + ch0]         = __float2bfloat16(v00);
                g_q[(size_t)(b * N_ + pos + 1) * 16 + ch0]     = __float2bfloat16(v01);
                g_q[(size_t)(b * N_ + pos) * 16 + ch0 + 8]     = __float2bfloat16(v10);
                g_q[(size_t)(b * N_ + pos + 1) * 16 + ch0 + 8] = __float2bfloat16(v11);
            } else if (mf == 1) {
                int c = ch0 - 16;
                g_k[(size_t)(b * N_ + pos) * 16 + c]         = __float2bfloat16(v00);
                g_k[(size_t)(b * N_ + pos + 1) * 16 + c]     = __float2bfloat16(v01);
                g_k[(size_t)(b * N_ + pos) * 16 + c + 8]     = __float2bfloat16(v10);
                g_k[(size_t)(b * N_ + pos + 1) * 16 + c + 8] = __float2bfloat16(v11);
            } else {
                int c = ch0 - 32;
                uint32_t p0, p1;
                CVT_BF16X2_F32(p0, v00, v01);
                CVT_BF16X2_F32(p1, v10, v11);
                *(uint32_t*)(g_v + (size_t)(b * C_ + c) * N_ + pos)     = p0;
                *(uint32_t*)(g_v + (size_t)(b * C_ + c + 8) * N_ + pos) = p1;
            }
        }
    }
}

// ---------------------------------------------------------------------------
// Flash attention R15: 512 threads, 16 warps = 2 streams x (4 row-groups x
// 2 channel-halves). Warp (s, rg, jh): 32 rows x 64 output channels.
// S/exp DUPLICATED across the two jh warps of a row-group (cheap) so every
// V-fragment ldsm feeds 4 HMMAs (crossbar -44%) while keeping 16 warps and
// O at 64 regs (fits the 128-reg cap). Rowsum MMAs only on jh=0 warps.
// Normalization folded into the final global loop via an inv table.
// ---------------------------------------------------------------------------
#define VS_OFF 0
#define VS_BUF 34816
#define KS_OFF (4 * VS_BUF)            /* 139264 */
#define KS_BUF 4096
#define QS_OFF (KS_OFF + 4 * KS_BUF)   /* 155648 */
#define LS_OFF (QS_OFF + 4096)         /* 159744: Ls1[128] | LsInv[128] */
#define ATTN_SM_BYTES (LS_OFF + 1024)

__global__ __launch_bounds__(512, 1)
void attn_kernel(const float* __restrict__ x, const float* __restrict__ gamma,
                 float* __restrict__ out) {
    char* sm = dyn_smem;
    const uint32_t smb = smem_to_u32(sm);

    const int tid = threadIdx.x;
    const int w   = tid >> 5;
    const int l   = tid & 31;
    const int gr  = l >> 2;
    const int qd  = l & 3;
    const int grp = l >> 3;
    const int lr  = l & 7;
    const int s   = w >> 3;        // stream 0/1
    const int ws  = w & 7;
    const int rg  = ws >> 1;       // row-group: rows 32*rg .. +31
    const int jh  = ws & 1;        // output channel half
    const int st  = tid & 255;     // thread within stream
    const int b   = blockIdx.y;
    const int i0  = blockIdx.x * 128;

    // ---- prologue: Q + first tile (j-tile index = s) per stream ----
    if (tid < 256) {
        int row = tid >> 1, half = tid & 1;
        cp_async16(smb + QS_OFF + row * 32 + half * 16,
                   (const char*)g_q + ((size_t)(b * N_ + i0 + row) * 16 + half * 8) * 2);
    }
    {
        const int j0 = s * 128;
        int row = st >> 1, half = st & 1;
        cp_async16(smb + KS_OFF + (2 * s) * KS_BUF + row * 32 + half * 16,
                   (const char*)g_k + ((size_t)(b * N_ + j0 + row) * 16 + half * 8) * 2);
        int rb = st >> 4, col = st & 15;
        #pragma unroll
        for (int u = 0; u < 8; u++) {
            int r = rb + 16 * u;
            cp_async16(smb + VS_OFF + (2 * s) * VS_BUF + r * 272 + col * 16,
                       (const char*)g_v + ((size_t)(b * C_ + r) * N_ + j0 + col * 8) * 2);
        }
        cp_commit();
    }
    cp_wait0();
    __syncthreads();

    // Q A-fragments for this warp's 32 rows (two m16 groups)
    uint32_t qa2[2][4];
    #pragma unroll
    for (int rg2 = 0; rg2 < 2; rg2++) {
        uint32_t qb = smb + QS_OFF + (32 * rg + 16 * rg2 + gr) * 32 + qd * 4;
        qa2[rg2][0] = lds32(qb);
        qa2[rg2][1] = lds32(qb + 8 * 32);
        qa2[rg2][2] = lds32(qb + 16);
        qa2[rg2][3] = lds32(qb + 8 * 32 + 16);
    }

    const uint32_t klane = (8 * (grp >> 1) + lr) * 32 + 16 * (grp & 1);
    const uint32_t vlane = (8 * (grp >> 1) + lr) * 272 + 16 * (grp & 1);

    float O0[8][4], O1[8][4];     // rg2=0 / rg2=1 rows, 64 channels (this jh)
    #pragma unroll
    for (int nt = 0; nt < 8; nt++)
        #pragma unroll
        for (int i = 0; i < 4; i++) { O0[nt][i] = 0.f; O1[nt][i] = 0.f; }
    float ls0[4] = {0.f, 0.f, 0.f, 0.f};
    float ls1[4] = {0.f, 0.f, 0.f, 0.f};

    #pragma unroll 1
    for (int jt = 0; jt < 16; jt++) {
        const int buf = jt & 1;
        const uint32_t kb = smb + KS_OFF + (2 * s + buf) * KS_BUF;
        const uint32_t vb = smb + VS_OFF + (2 * s + buf) * VS_BUF;

        if (jt + 1 < 16) {
            const int j1 = (2 * (jt + 1) + s) * 128;
            const int nb = buf ^ 1;
            int row = st >> 1, half = st & 1;
            cp_async16(smb + KS_OFF + (2 * s + nb) * KS_BUF + row * 32 + half * 16,
                       (const char*)g_k + ((size_t)(b * N_ + j1 + row) * 16 + half * 8) * 2);
            int rb = st >> 4, col = st & 15;
            #pragma unroll
            for (int u = 0; u < 8; u++) {
                int r = rb + 16 * u;
                cp_async16(smb + VS_OFF + (2 * s + nb) * VS_BUF + r * 272 + col * 16,
                           (const char*)g_v + ((size_t)(b * C_ + r) * N_ + j1 + col * 8) * 2);
            }
            cp_commit();
        }

        #pragma unroll
        for (int ks = 0; ks < 8; ks++) {
            // K-fragment serves both row groups
            uint32_t kr[4];
            ldsm_x4(kr, kb + klane + ks * 512);
            float sa0[4] = {0.f, 0.f, 0.f, 0.f};
            float sa1[4] = {0.f, 0.f, 0.f, 0.f};
            float sb0[4] = {0.f, 0.f, 0.f, 0.f};
            float sb1[4] = {0.f, 0.f, 0.f, 0.f};
            mma16816(sa0, qa2[0], kr[0], kr[1]);
            mma16816(sa1, qa2[0], kr[2], kr[3]);
            mma16816(sb0, qa2[1], kr[0], kr[1]);
            mma16816(sb1, qa2[1], kr[2], kr[3]);

            // packed exp for both row groups (duplicated across jh pair)
            uint32_t Pf0[4], Pf1[4];
            CVT_BF16X2_F32(Pf0[0], sa0[0], sa0[1]);
            CVT_BF16X2_F32(Pf0[1], sa0[2], sa0[3]);
            CVT_BF16X2_F32(Pf0[2], sa1[0], sa1[1]);
            CVT_BF16X2_F32(Pf0[3], sa1[2], sa1[3]);
            CVT_BF16X2_F32(Pf1[0], sb0[0], sb0[1]);
            CVT_BF16X2_F32(Pf1[1], sb0[2], sb0[3]);
            CVT_BF16X2_F32(Pf1[2], sb1[0], sb1[1]);
            CVT_BF16X2_F32(Pf1[3], sb1[2], sb1[3]);
            Pf0[0] = ex2_bf16x2(Pf0[0]);
            Pf0[1] = ex2_bf16x2(Pf0[1]);
            Pf0[2] = ex2_bf16x2(Pf0[2]);
            Pf0[3] = ex2_bf16x2(Pf0[3]);
            Pf1[0] = ex2_bf16x2(Pf1[0]);
            Pf1[1] = ex2_bf16x2(Pf1[1]);
            Pf1[2] = ex2_bf16x2(Pf1[2]);
            Pf1[3] = ex2_bf16x2(Pf1[3]);

            // rowsums: only jh==0 warps (dedup)
            if (jh == 0) {
                mma16816(ls0, Pf0, ONES_BF16X2, ONES_BF16X2);
                mma16816(ls1, Pf1, ONES_BF16X2, ONES_BF16X2);
            }

            // MMA2: 4 ldsm, each feeding 4 HMMAs (both row groups)
            #pragma unroll
            for (int ntp = 0; ntp < 4; ntp++) {
                uint32_t vr[4];
                ldsm_x4(vr, vb + vlane + (uint32_t)(4 * jh + ntp) * 4352 + ks * 32);
                mma16816(O0[2 * ntp],     Pf0, vr[0], vr[1]);
                mma16816(O0[2 * ntp + 1], Pf0, vr[2], vr[3]);
                mma16816(O1[2 * ntp],     Pf1, vr[0], vr[1]);
                mma16816(O1[2 * ntp + 1], Pf1, vr[2], vr[3]);
            }
        }

        if (jt + 1 < 16) {
            cp_wait0();
            bar_sync(1 + s, 256);
        }
    }

    // ---- epilogue ----
    __syncthreads();

    float* Osm   = (float*)sm;                 // [128][129] over Vs region
    float* Ls1   = (float*)(sm + LS_OFF);      // stream-1 rowsums [128]
    float* LsInv = Ls1 + 128;                  // 1/total rowsum [128]
    const int rA = 32 * rg + gr;               // rg2=0 rows: rA, rA+8
    const int rB = rA + 16;                    // rg2=1 rows: rB, rB+8

    if (s == 1) {
        if (jh == 0 && qd == 0) {
            Ls1[rA]     = ls0[0];
            Ls1[rA + 8] = ls0[2];
            Ls1[rB]     = ls1[0];
            Ls1[rB + 8] = ls1[2];
        }
        #pragma unroll
        for (int nt = 0; nt < 8; nt++) {
            int c = 64 * jh + 8 * nt + 2 * qd;
            Osm[rA * 129 + c]           = O0[nt][0];
            Osm[rA * 129 + c + 1]       = O0[nt][1];
            Osm[(rA + 8) * 129 + c]     = O0[nt][2];
            Osm[(rA + 8) * 129 + c + 1] = O0[nt][3];
            Osm[rB * 129 + c]           = O1[nt][0];
            Osm[rB * 129 + c + 1]       = O1[nt][1];
            Osm[(rB + 8) * 129 + c]     = O1[nt][2];
            Osm[(rB + 8) * 129 + c + 1] = O1[nt][3];
        }
    }
    __syncthreads();
    if (s == 0) {
        if (jh == 0 && qd == 0) {
            LsInv[rA]     = 1.0f / (ls0[0] + Ls1[rA]);
            LsInv[rA + 8] = 1.0f / (ls0[2] + Ls1[rA + 8]);
            LsInv[rB]     = 1.0f / (ls1[0] + Ls1[rB]);
            LsInv[rB + 8] = 1.0f / (ls1[2] + Ls1[rB + 8]);
        }
        #pragma unroll
        for (int nt = 0; nt < 8; nt++) {
            int c = 64 * jh + 8 * nt + 2 * qd;
            Osm[rA * 129 + c]           += O0[nt][0];
            Osm[rA * 129 + c + 1]       += O0[nt][1];
            Osm[(rA + 8) * 129 + c]     += O0[nt][2];
            Osm[(rA + 8) * 129 + c + 1] += O0[nt][3];
            Osm[rB * 129 + c]           += O1[nt][0];
            Osm[rB * 129 + c + 1]       += O1[nt][1];
            Osm[(rB + 8) * 129 + c]     += O1[nt][2];
            Osm[(rB + 8) * 129 + c + 1] += O1[nt][3];
        }
    }
    __syncthreads();

    const float gm = gamma[0];
    #pragma unroll 4
    for (int it = 0; it < 32; it++) {
        int idx = tid + 512 * it;
        int c = idx >> 7, il = idx & 127;
        size_t gi = (size_t)(b * C_ + c) * N_ + i0 + il;
        out[gi] = gm * Osm[il * 129 + c] * LsInv[il] + x[gi];
    }
}

// ---------------------------------------------------------------------------
extern "C" void kernel_launch(void* const* d_in, const int* in_sizes, int n_in,
                              void* d_out, int out_size) {
    (void)in_sizes; (void)n_in; (void)out_size;
    const float* x     = (const float*)d_in[0];
    const float* wq    = (const float*)d_in[1];
    const float* bq    = (const float*)d_in[2];
    const float* wk    = (const float*)d_in[3];
    const float* bk    = (const float*)d_in[4];
    const float* wv    = (const float*)d_in[5];
    const float* bv    = (const float*)d_in[6];
    const float* gamma = (const float*)d_in[7];
    float* out = (float*)d_out;

    cudaFuncSetAttribute(proj_kernel, cudaFuncAttributeMaxDynamicSharedMemorySize,
                         PROJ_SM_BYTES);
    cudaFuncSetAttribute(attn_kernel, cudaFuncAttributeMaxDynamicSharedMemorySize,
                         ATTN_SM_BYTES);

    proj_kernel<<<dim3(32, 4), 256, PROJ_SM_BYTES>>>(x, wq, bq, wk, bk, wv, bv);
    attn_kernel<<<dim3(32, 4), 512, ATTN_SM_BYTES>>>(x, gamma, out);
}

// round 16
// speedup vs baseline: 1.1261x; 1.1261x over previous
#include <cuda_runtime.h>
#include <cuda_bf16.h>
#include <cstdint>

#define B_   4
#define C_   128
#define CQ_  16
#define N_   4096

__device__ __nv_bfloat16 g_q[B_ * N_ * CQ_];   // [B][N][16]  (q pre-scaled by log2e)
__device__ __nv_bfloat16 g_k[B_ * N_ * CQ_];   // [B][N][16]
__device__ __nv_bfloat16 g_v[B_ * C_ * N_];    // [B][C][N]  (channel-major)

extern __shared__ char dyn_smem[];

// ---------------------------------------------------------------------------
// Helpers
// ---------------------------------------------------------------------------
__device__ __forceinline__ uint32_t smem_to_u32(const void* p) {
    uint32_t a;
    asm("{ .reg .u64 t; cvta.to.shared.u64 t, %1; cvt.u32.u64 %0, t; }"
        : "=r"(a) : "l"(p));
    return a;
}
__device__ __forceinline__ void cp_async16(uint32_t dst, const void* src) {
    asm volatile("cp.async.cg.shared.global [%0], [%1], 16;"
                 :: "r"(dst), "l"(src) : "memory");
}
__device__ __forceinline__ void cp_commit() {
    asm volatile("cp.async.commit_group;" ::: "memory");
}
__device__ __forceinline__ void cp_wait0() {
    asm volatile("cp.async.wait_group 0;" ::: "memory");
}
__device__ __forceinline__ void cp_wait1() {
    asm volatile("cp.async.wait_group 1;" ::: "memory");
}
__device__ __forceinline__ void cp_wait2() {
    asm volatile("cp.async.wait_group 2;" ::: "memory");
}
__device__ __forceinline__ uint32_t lds32(uint32_t addr) {
    uint32_t v;
    asm volatile("ld.shared.b32 %0, [%1];" : "=r"(v) : "r"(addr));
    return v;
}
__device__ __forceinline__ void ldsm_x4(uint32_t* r, uint32_t addr) {
    asm volatile("ldmatrix.sync.aligned.m8n8.x4.shared.b16 {%0,%1,%2,%3}, [%4];"
                 : "=r"(r[0]), "=r"(r[1]), "=r"(r[2]), "=r"(r[3]) : "r"(addr));
}
__device__ __forceinline__ void ldsm_x4_trans(uint32_t* r, uint32_t addr) {
    asm volatile("ldmatrix.sync.aligned.m8n8.x4.trans.shared.b16 {%0,%1,%2,%3}, [%4];"
                 : "=r"(r[0]), "=r"(r[1]), "=r"(r[2]), "=r"(r[3]) : "r"(addr));
}
__device__ __forceinline__ void mma16816(float* d, const uint32_t* a,
                                         uint32_t b0, uint32_t b1) {
    asm volatile(
        "mma.sync.aligned.m16n8k16.row.col.f32.bf16.bf16.f32 "
        "{%0,%1,%2,%3}, {%4,%5,%6,%7}, {%8,%9}, {%0,%1,%2,%3};"
        : "+f"(d[0]), "+f"(d[1]), "+f"(d[2]), "+f"(d[3])
        : "r"(a[0]), "r"(a[1]), "r"(a[2]), "r"(a[3]), "r"(b0), "r"(b1));
}
__device__ __forceinline__ uint32_t ex2_bf16x2(uint32_t x) {
    uint32_t d;
    asm("ex2.approx.ftz.bf16x2 %0, %1;" : "=r"(d) : "r"(x));
    return d;
}
// pack: low half = a, high half = b
#define CVT_BF16X2_F32(result, a, b) \
    asm("cvt.rn.satfinite.bf16x2.f32 %0, %1, %2;" : "=r"(result) : "f"(b), "f"(a))

#define ONES_BF16X2 0x3F803F80u

// ---------------------------------------------------------------------------
// Projection on tensor cores (q pre-scaled by log2e) — unchanged
// ---------------------------------------------------------------------------
#define PJ_WS   0
#define PJ_XS   43520
#define PJ_BS   78336
#define PROJ_SM_BYTES (PJ_BS + 640)
#define LOG2E_F 1.44269504088896f

__global__ __launch_bounds__(256, 1)
void proj_kernel(const float* __restrict__ x,
                 const float* __restrict__ wq, const float* __restrict__ bq,
                 const float* __restrict__ wk, const float* __restrict__ bk,
                 const float* __restrict__ wv, const float* __restrict__ bv) {
    char* sm = dyn_smem;
    const uint32_t smb = smem_to_u32(sm);
    __nv_bfloat16* Ws = (__nv_bfloat16*)(sm + PJ_WS);
    __nv_bfloat16* Xs = (__nv_bfloat16*)(sm + PJ_XS);
    float* Bs = (float*)(sm + PJ_BS);

    const int tid = threadIdx.x;
    const int b   = blockIdx.y;
    const int n0  = blockIdx.x * 128;

    for (int idx = tid; idx < 160 * 32; idx += 256) {
        int ch = idx >> 5, cq = (idx & 31) * 4;
        const float* wsrc = (ch < 16) ? (wq + ch * 128 + cq)
                          : (ch < 32) ? (wk + (ch - 16) * 128 + cq)
                                      : (wv + (ch - 32) * 128 + cq);
        float4 wv4 = *(const float4*)wsrc;
        if (ch < 16) {
            wv4.x *= LOG2E_F; wv4.y *= LOG2E_F;
            wv4.z *= LOG2E_F; wv4.w *= LOG2E_F;
        }
        uint32_t p0, p1;
        CVT_BF16X2_F32(p0, wv4.x, wv4.y);
        CVT_BF16X2_F32(p1, wv4.z, wv4.w);
        *(uint2*)(Ws + ch * 136 + cq) = make_uint2(p0, p1);
    }
    if (tid < 160)
        Bs[tid] = (tid < 16) ? (bq[tid] * LOG2E_F)
                : (tid < 32) ? bk[tid - 16] : bv[tid - 32];

    const float* xb = x + (size_t)b * C_ * N_ + n0;
    for (int idx = tid; idx < 128 * 32; idx += 256) {
        int c = idx >> 5, jq = (idx & 31) * 4;
        float4 xv = *(const float4*)(xb + (size_t)c * N_ + jq);
        uint32_t p0, p1;
        CVT_BF16X2_F32(p0, xv.x, xv.y);
        CVT_BF16X2_F32(p1, xv.z, xv.w);
        *(uint2*)(Xs + c * 136 + jq) = make_uint2(p0, p1);
    }
    __syncthreads();

    const int w  = tid >> 5;
    const int l  = tid & 31;
    const int gr = l >> 2, qd = l & 3;
    const int grp = l >> 3, lr = l & 7;
    const int nw = 16 * w;

    float acc[10][2][4];
    #pragma unroll
    for (int mf = 0; mf < 10; mf++)
        #pragma unroll
        for (int nf = 0; nf < 2; nf++)
            #pragma unroll
            for (int i = 0; i < 4; i++) acc[mf][nf][i] = 0.f;

    const uint32_t xbase = smb + PJ_XS
        + (uint32_t)((grp & 1) * 8 + lr) * 272u + (uint32_t)(nw + (grp >> 1) * 8) * 2u;
    const uint32_t wbase = smb + PJ_WS
        + (uint32_t)((grp & 1) * 8 + lr) * 272u + (uint32_t)((grp >> 1) * 8) * 2u;

    #pragma unroll
    for (int kk = 0; kk < 8; kk++) {
        uint32_t bx[4];
        ldsm_x4_trans(bx, xbase + kk * 16 * 272u);
        #pragma unroll
        for (int mf = 0; mf < 10; mf++) {
            uint32_t aw[4];
            ldsm_x4(aw, wbase + (uint32_t)(mf * 16) * 272u + kk * 32u);
            mma16816(acc[mf][0], aw, bx[0], bx[1]);
            mma16816(acc[mf][1], aw, bx[2], bx[3]);
        }
    }

    #pragma unroll
    for (int mf = 0; mf < 10; mf++) {
        int ch0 = 16 * mf + gr;
        float b0 = Bs[ch0], b1 = Bs[ch0 + 8];
        #pragma unroll
        for (int nf = 0; nf < 2; nf++) {
            int pos = n0 + nw + 8 * nf + 2 * qd;
            float v00 = acc[mf][nf][0] + b0, v01 = acc[mf][nf][1] + b0;
            float v10 = acc[mf][nf][2] + b1, v11 = acc[mf][nf][3] + b1;
            if (mf == 0) {
                g_q[(size_t)(b * N_ + pos) * 16 + ch0]         = __float2bfloat16(v00);
                g_q[(size_t)(b * N_ + pos + 1) * 16 + ch0]     = __float2bfloat16(v01);
                g_q[(size_t)(b * N_ + pos) * 16 + ch0 + 8]     = __float2bfloat16(v10);
                g_q[(size_t)(b * N_ + pos + 1) * 16 + ch0 + 8] = __float2bfloat16(v11);
            } else if (mf == 1) {
                int c = ch0 - 16;
                g_k[(size_t)(b * N_ + pos) * 16 + c]         = __float2bfloat16(v00);
                g_k[(size_t)(b * N_ + pos + 1) * 16 + c]     = __float2bfloat16(v01);
                g_k[(size_t)(b * N_ + pos) * 16 + c + 8]     = __float2bfloat16(v10);
                g_k[(size_t)(b * N_ + pos + 1) * 16 + c + 8] = __float2bfloat16(v11);
            } else {
                int c = ch0 - 32;
                uint32_t p0, p1;
                CVT_BF16X2_F32(p0, v00, v01);
                CVT_BF16X2_F32(p1, v10, v11);
                *(uint32_t*)(g_v + (size_t)(b * C_ + c) * N_ + pos)     = p0;
                *(uint32_t*)(g_v + (size_t)(b * C_ + c + 8) * N_ + pos) = p1;
            }
        }
    }
}

// ---------------------------------------------------------------------------
// Flash attention R16: 512 threads, single j-stream, 16 warps =
// (8 row-groups x 2 j-halves). Warp (rg, jh): 16 rows x 64-j half x 128 ch.
// Per-warp ldsm/HMMA totals identical to R12; only synchronization relaxed:
// 4-deep K/V pipeline, prefetch distance 2 (wait_group 2), barrier every
// 2 tiles -> warps drift up to 1 tile, overlapping MMA1/exp (tensor+MUFU)
// with MMA2 (crossbar) across warps. bf16x2 exp + tensor-core row-sums.
// smem: Vs 4x34816 | Ks 4x4096 @139264 | Qs @155648 | Ls @159744.
// ---------------------------------------------------------------------------
#define VS_OFF 0
#define VS_BUF 34816
#define KS_OFF (4 * VS_BUF)            /* 139264 */
#define KS_BUF 4096
#define QS_OFF (KS_OFF + 4 * KS_BUF)   /* 155648 */
#define LS_OFF (QS_OFF + 4096)         /* 159744 */
#define ATTN_SM_BYTES (LS_OFF + 512)

__global__ __launch_bounds__(512, 1)
void attn_kernel(const float* __restrict__ x, const float* __restrict__ gamma,
                 float* __restrict__ out) {
    char* sm = dyn_smem;
    const uint32_t smb = smem_to_u32(sm);

    const int tid = threadIdx.x;
    const int w   = tid >> 5;
    const int l   = tid & 31;
    const int gr  = l >> 2;
    const int qd  = l & 3;
    const int grp = l >> 3;
    const int lr  = l & 7;
    const int rg  = w >> 1;        // row group: rows 16*rg .. +15
    const int jh  = w & 1;         // j half of each tile
    const int b   = blockIdx.y;
    const int i0  = blockIdx.x * 128;

    // ---- prologue: Q + tiles 0 and 1 (two commit groups) ----
    if (tid < 256) {
        int row = tid >> 1, half = tid & 1;
        cp_async16(smb + QS_OFF + row * 32 + half * 16,
                   (const char*)g_q + ((size_t)(b * N_ + i0 + row) * 16 + half * 8) * 2);
    }
    #pragma unroll
    for (int pt = 0; pt < 2; pt++) {
        const int j0 = pt * 128;
        if (tid < 256) {
            int row = tid >> 1, half = tid & 1;
            cp_async16(smb + KS_OFF + pt * KS_BUF + row * 32 + half * 16,
                       (const char*)g_k + ((size_t)(b * N_ + j0 + row) * 16 + half * 8) * 2);
        }
        #pragma unroll
        for (int u = 0; u < 4; u++) {
            int idx = tid + 512 * u;
            int r = idx >> 4, col = idx & 15;
            cp_async16(smb + VS_OFF + pt * VS_BUF + r * 272 + col * 16,
                       (const char*)g_v + ((size_t)(b * C_ + r) * N_ + j0 + col * 8) * 2);
        }
        cp_commit();
    }
    __syncthreads();   // Q visible (Q rides in group 0; wait below covers it)

    // Q A-fragment for this warp's 16 rows  (after group-0 completes)
    cp_wait1();        // group 0 (Q + tile 0) complete
    __syncthreads();
    uint32_t qa[4];
    {
        uint32_t qb = smb + QS_OFF + (16 * rg + gr) * 32 + qd * 4;
        qa[0] = lds32(qb);
        qa[1] = lds32(qb + 8 * 32);
        qa[2] = lds32(qb + 16);
        qa[3] = lds32(qb + 8 * 32 + 16);
    }

    const uint32_t klane = (8 * (grp >> 1) + lr) * 32 + 16 * (grp & 1);
    const uint32_t vlane = (8 * (grp >> 1) + lr) * 272 + 16 * (grp & 1);

    float O[16][4];
    #pragma unroll
    for (int nt = 0; nt < 16; nt++)
        #pragma unroll
        for (int i = 0; i < 4; i++) O[nt][i] = 0.f;
    float ls[4] = {0.f, 0.f, 0.f, 0.f};

    #pragma unroll 1
    for (int t = 0; t < 32; t++) {
        // buffer-reuse guard every 2 tiles (allows 1-tile warp drift)
        if (t >= 2 && (t & 1) == 0) __syncthreads();

        // prefetch tile t+2
        if (t + 2 < 32) {
            const int j1 = (t + 2) * 128;
            const int nb = (t + 2) & 3;
            if (tid < 256) {
                int row = tid >> 1, half = tid & 1;
                cp_async16(smb + KS_OFF + nb * KS_BUF + row * 32 + half * 16,
                           (const char*)g_k + ((size_t)(b * N_ + j1 + row) * 16 + half * 8) * 2);
            }
            #pragma unroll
            for (int u = 0; u < 4; u++) {
                int idx = tid + 512 * u;
                int r = idx >> 4, col = idx & 15;
                cp_async16(smb + VS_OFF + nb * VS_BUF + r * 272 + col * 16,
                           (const char*)g_v + ((size_t)(b * C_ + r) * N_ + j1 + col * 8) * 2);
            }
            cp_commit();
        }

        // tile t must be resident
        if (t + 2 < 32) cp_wait2();
        else if (t + 1 < 32) cp_wait1();
        else cp_wait0();

        const uint32_t kb = smb + KS_OFF + (uint32_t)(t & 3) * KS_BUF
                          + (uint32_t)jh * 2048u;
        const uint32_t vb = smb + VS_OFF + (uint32_t)(t & 3) * VS_BUF
                          + (uint32_t)jh * 128u;

        #pragma unroll
        for (int c = 0; c < 4; c++) {
            uint32_t kr[4];
            ldsm_x4(kr, kb + klane + c * 512);
            float sa0[4] = {0.f, 0.f, 0.f, 0.f};
            float sa1[4] = {0.f, 0.f, 0.f, 0.f};
            mma16816(sa0, qa, kr[0], kr[1]);
            mma16816(sa1, qa, kr[2], kr[3]);

            uint32_t Pf[4];
            CVT_BF16X2_F32(Pf[0], sa0[0], sa0[1]);
            CVT_BF16X2_F32(Pf[1], sa0[2], sa0[3]);
            CVT_BF16X2_F32(Pf[2], sa1[0], sa1[1]);
            CVT_BF16X2_F32(Pf[3], sa1[2], sa1[3]);
            Pf[0] = ex2_bf16x2(Pf[0]);
            Pf[1] = ex2_bf16x2(Pf[1]);
            Pf[2] = ex2_bf16x2(Pf[2]);
            Pf[3] = ex2_bf16x2(Pf[3]);

            mma16816(ls, Pf, ONES_BF16X2, ONES_BF16X2);

            #pragma unroll
            for (int ntp = 0; ntp < 8; ntp++) {
                uint32_t vr[4];
                ldsm_x4(vr, vb + vlane + ntp * 4352 + c * 32);
                mma16816(O[2 * ntp],     Pf, vr[0], vr[1]);
                mma16816(O[2 * ntp + 1], Pf, vr[2], vr[3]);
            }
        }
    }

    // ---- epilogue: merge jh halves, normalize, residual ----
    __syncthreads();

    float* Osm = (float*)sm;                 // [128][129] over Vs region
    float* Ls1 = (float*)(sm + LS_OFF);      // jh=1 partial rowsums [128]
    const int r0 = 16 * rg + gr, r1 = r0 + 8;

    if (jh == 1) {
        if (qd == 0) { Ls1[r0] = ls[0]; Ls1[r1] = ls[2]; }
        #pragma unroll
        for (int nt = 0; nt < 16; nt++) {
            int c = 8 * nt + 2 * qd;
            Osm[r0 * 129 + c]     = O[nt][0];
            Osm[r0 * 129 + c + 1] = O[nt][1];
            Osm[r1 * 129 + c]     = O[nt][2];
            Osm[r1 * 129 + c + 1] = O[nt][3];
        }
    }
    __syncthreads();
    if (jh == 0) {
        const float inv0 = 1.0f / (ls[0] + Ls1[r0]);
        const float inv1 = 1.0f / (ls[2] + Ls1[r1]);
        #pragma unroll
        for (int nt = 0; nt < 16; nt++) {
            int c = 8 * nt + 2 * qd;
            Osm[r0 * 129 + c]     = (Osm[r0 * 129 + c]     + O[nt][0]) * inv0;
            Osm[r0 * 129 + c + 1] = (Osm[r0 * 129 + c + 1] + O[nt][1]) * inv0;
            Osm[r1 * 129 + c]     = (Osm[r1 * 129 + c]     + O[nt][2]) * inv1;
            Osm[r1 * 129 + c + 1] = (Osm[r1 * 129 + c + 1] + O[nt][3]) * inv1;
        }
    }
    __syncthreads();

    const float gm = gamma[0];
    #pragma unroll 4
    for (int it = 0; it < 32; it++) {
        int idx = tid + 512 * it;
        int c = idx >> 7, il = idx & 127;
        size_t gi = (size_t)(b * C_ + c) * N_ + i0 + il;
        out[gi] = gm * Osm[il * 129 + c] + x[gi];
    }
}

// ---------------------------------------------------------------------------
extern "C" void kernel_launch(void* const* d_in, const int* in_sizes, int n_in,
                              void* d_out, int out_size) {
    (void)in_sizes; (void)n_in; (void)out_size;
    const float* x     = (const float*)d_in[0];
    const float* wq    = (const float*)d_in[1];
    const float* bq    = (const float*)d_in[2];
    const float* wk    = (const float*)d_in[3];
    const float* bk    = (const float*)d_in[4];
    const float* wv    = (const float*)d_in[5];
    const float* bv    = (const float*)d_in[6];
    const float* gamma = (const float*)d_in[7];
    float* out = (float*)d_out;

    cudaFuncSetAttribute(proj_kernel, cudaFuncAttributeMaxDynamicSharedMemorySize,
                         PROJ_SM_BYTES);
    cudaFuncSetAttribute(attn_kernel, cudaFuncAttributeMaxDynamicSharedMemorySize,
                         ATTN_SM_BYTES);

    proj_kernel<<<dim3(32, 4), 256, PROJ_SM_BYTES>>>(x, wq, bq, wk, bk, wv, bv);
    attn_kernel<<<dim3(32, 4), 512, ATTN_SM_BYTES>>>(x, gamma, out);
}